// round 17
// baseline (speedup 1.0000x reference)
#include <cuda_runtime.h>
#include <cuda_bf16.h>

// FrozenBNBStableEmbedding: blockwise-int8 dequant embedding gather + LayerNorm.
//
// Inputs (metadata order):
//   0: x         int32  [8, 2048]    token ids (16384)
//   1: weight_i8 int32  [50304,1024] code indices 0..255
//   2: absmax    f32    [12576]      per-4096-elem block scale == per (row>>2)
//   3: code      f32    [256]        dequant codebook
//   4: ln_weight f32    [1024]
//   5: ln_bias   f32    [1024]
// Output: f32 [8, 2048, 1024]
//
// WARP-PER-TOKEN, PERSISTENT, cp.async-STAGED DOUBLE BUFFER:
//   - each token's 4 KB of codes staged GMEM->SMEM via cp.async (LDGSTS):
//     gather payload never occupies registers while in flight
//   - per-warp ring of 2 stages -> 2 tokens always in flight per warp
//     (16 warps/SM x 8 KB = 128 KB gather bytes in flight per SM)
//   - exactly one cp.async.commit_group per iteration (empty at the tail)
//     so cp.async.wait_group 1 always means "oldest stage ready"
//   - codebook replicated 32x in shared: bank == lane, conflict-free
//   - zero block barriers in the main loop (warp shfl reductions only)
//   - 104 KB dynamic smem -> 2 CTAs/SM; grid = 296 (one persistent wave)

#define D 1024
#define V 50304
#define EPS 1e-5f
#define WARPS_PER_CTA 8
#define STAGE_BYTES 4096
#define SMEM_REP_OFF   0          // 32 KB: replicated codebook
#define SMEM_W_OFF     32768      // 4 KB : ln_weight (float4)
#define SMEM_B_OFF     36864      // 4 KB : ln_bias   (float4)
#define SMEM_STAGE_OFF 40960      // 64 KB: 8 warps x 2 stages x 4 KB
#define SMEM_TOTAL     106496     // 104 KB

extern __shared__ char dsm[];

__device__ __forceinline__ void cp_async16(unsigned smem_addr, const void* gptr) {
    asm volatile("cp.async.cg.shared.global [%0], [%1], 16;"
                 :: "r"(smem_addr), "l"(gptr) : "memory");
}
__device__ __forceinline__ void cp_commit() {
    asm volatile("cp.async.commit_group;" ::: "memory");
}
__device__ __forceinline__ void cp_wait1() {
    asm volatile("cp.async.wait_group 1;" ::: "memory");
}

__global__ __launch_bounds__(256, 2)
void frozen_bnb_emb_ln_kernel(const int* __restrict__ x,
                              const int* __restrict__ weight_i8,
                              const float* __restrict__ absmax,
                              const float* __restrict__ code,
                              const float* __restrict__ ln_weight,
                              const float* __restrict__ ln_bias,
                              float* __restrict__ out,
                              int n_tokens)
{
    float*  s_rep = reinterpret_cast<float*> (dsm + SMEM_REP_OFF);
    float4* s_w   = reinterpret_cast<float4*>(dsm + SMEM_W_OFF);
    float4* s_b   = reinterpret_cast<float4*>(dsm + SMEM_B_OFF);
    char*   s_stg = dsm + SMEM_STAGE_OFF;

    const int tid  = threadIdx.x;
    const int warp = tid >> 5;
    const int lane = tid & 31;

    // ---- One-time staging (only barrier in the kernel) ----
    {
        const float cv = __ldg(&code[tid]);
        float* row = &s_rep[tid * 32];
        #pragma unroll
        for (int k = 0; k < 32; k++)
            row[(lane + k) & 31] = cv;           // distinct bank per lane
        s_w[tid] = __ldg(reinterpret_cast<const float4*>(ln_weight) + tid);
        s_b[tid] = __ldg(reinterpret_cast<const float4*>(ln_bias) + tid);
    }
    __syncthreads();

    const int stride = gridDim.x * WARPS_PER_CTA;    // total warps (persistent)
    int tok = blockIdx.x * WARPS_PER_CTA + warp;
    if (tok >= n_tokens) return;                     // never true at grid=296

    // Per-warp stage bases (generic + shared-space address per stage)
    char*    stg_ptr[2];
    unsigned stg_u32[2];
    #pragma unroll
    for (int s = 0; s < 2; s++) {
        stg_ptr[s] = s_stg + (warp * 2 + s) * STAGE_BYTES;
        stg_u32[s] = (unsigned)__cvta_generic_to_shared(stg_ptr[s]);
    }
    const unsigned lane_off = lane * 16u;            // chunk j at (j*512 + lane*16)

    // ---- Prologue: fill stage 0 (tok) and stage 1 (tok+stride) ----
    float scaleA, scaleB = 0.0f;
    {
        int r = min(max(__ldg(&x[tok]), 0), V - 1);
        scaleA = __ldg(&absmax[r >> 2]);
        const char* wr = reinterpret_cast<const char*>(weight_i8 + (long long)r * D);
        #pragma unroll
        for (int j = 0; j < 8; j++)
            cp_async16(stg_u32[0] + j * 512u + lane_off, wr + j * 512 + lane_off);
    }
    cp_commit();                                     // group #0 (stage 0)
    if (tok + stride < n_tokens) {
        int r = min(max(__ldg(&x[tok + stride]), 0), V - 1);
        scaleB = __ldg(&absmax[r >> 2]);
        const char* wr = reinterpret_cast<const char*>(weight_i8 + (long long)r * D);
        #pragma unroll
        for (int j = 0; j < 8; j++)
            cp_async16(stg_u32[1] + j * 512u + lane_off, wr + j * 512 + lane_off);
    }
    cp_commit();                                     // group #1 (stage 1, maybe empty)

    int p = 0;                                       // current stage parity
    while (true) {
        // ---- Oldest stage ready? (exactly one group committed per iter) ----
        cp_wait1();

        // ---- Read this token's codes from shared (conflict-free LDS.128) ----
        int4 c[8];
        const char* sp = stg_ptr[p];
        #pragma unroll
        for (int j = 0; j < 8; j++)
            c[j] = *reinterpret_cast<const int4*>(sp + j * 512 + lane_off);

        // ---- Pass 1: dequant lookups -> v[32] (unscaled), stats ----
        float v[32];
        float s = 0.0f, sq = 0.0f;
        #pragma unroll
        for (int j = 0; j < 8; j++) {
            float a0 = s_rep[(c[j].x & 255) * 32 + lane];
            float a1 = s_rep[(c[j].y & 255) * 32 + lane];
            float a2 = s_rep[(c[j].z & 255) * 32 + lane];
            float a3 = s_rep[(c[j].w & 255) * 32 + lane];
            v[4*j+0] = a0; v[4*j+1] = a1; v[4*j+2] = a2; v[4*j+3] = a3;
            s  += a0 + a1 + a2 + a3;
            sq += a0*a0 + a1*a1 + a2*a2 + a3*a3;
        }

        // ---- Refill this stage for token t+2 (codes already consumed) ----
        const int tok2 = tok + 2 * stride;
        float nscale = 0.0f;
        if (tok2 < n_tokens) {
            int r = min(max(__ldg(&x[tok2]), 0), V - 1);
            nscale = __ldg(&absmax[r >> 2]);
            const char* wr = reinterpret_cast<const char*>(weight_i8 + (long long)r * D);
            #pragma unroll
            for (int j = 0; j < 8; j++)
                cp_async16(stg_u32[p] + j * 512u + lane_off, wr + j * 512 + lane_off);
        }
        cp_commit();                                 // always exactly one group

        // ---- Warp-only LayerNorm stats (scale folded in afterwards) ----
        #pragma unroll
        for (int off = 16; off > 0; off >>= 1) {
            s  += __shfl_xor_sync(0xFFFFFFFFu, s,  off);
            sq += __shfl_xor_sync(0xFFFFFFFFu, sq, off);
        }
        const float mean_u = s * (1.0f / D);
        const float var    = (sq * (1.0f / D) - mean_u * mean_u) * scaleA * scaleA;
        const float rstd   = rsqrtf(var + EPS);
        const float a_mul  = scaleA * rstd;
        const float a_sub  = mean_u * scaleA * rstd;

        // ---- Affine + coalesced float4 stores ----
        float4* orow = reinterpret_cast<float4*>(out + (long long)tok * D);
        #pragma unroll
        for (int j = 0; j < 8; j++) {
            const float4 w4 = s_w[j * 32 + lane];
            const float4 b4 = s_b[j * 32 + lane];
            float4 o;
            o.x = (v[4*j+0] * a_mul - a_sub) * w4.x + b4.x;
            o.y = (v[4*j+1] * a_mul - a_sub) * w4.y + b4.y;
            o.z = (v[4*j+2] * a_mul - a_sub) * w4.z + b4.z;
            o.w = (v[4*j+3] * a_mul - a_sub) * w4.w + b4.w;
            orow[j * 32 + lane] = o;
        }

        if (tok + stride >= n_tokens) break;
        tok += stride;
        scaleA = scaleB;
        scaleB = nscale;
        p ^= 1;
    }
}

extern "C" void kernel_launch(void* const* d_in, const int* in_sizes, int n_in,
                              void* d_out, int out_size)
{
    const int*   x      = (const int*)d_in[0];
    const int*   w_i8   = (const int*)d_in[1];
    const float* absmax = (const float*)d_in[2];
    const float* code   = (const float*)d_in[3];
    const float* ln_w   = (const float*)d_in[4];
    const float* ln_b   = (const float*)d_in[5];
    float*       out    = (float*)d_out;

    const int n_tokens = in_sizes[0];   // 16384
    const int grid = 296;               // 2 CTAs/SM x 148 SMs: one persistent wave

    // Opt in to >48 KB dynamic shared (module state change; not an allocation,
    // not a stream operation — graph-capture safe; idempotent per call).
    cudaFuncSetAttribute(frozen_bnb_emb_ln_kernel,
                         cudaFuncAttributeMaxDynamicSharedMemorySize, SMEM_TOTAL);

    frozen_bnb_emb_ln_kernel<<<grid, 256, SMEM_TOTAL>>>(
        x, w_i8, absmax, code, ln_w, ln_b, out, n_tokens);
}